// round 2
// baseline (speedup 1.0000x reference)
#include <cuda_runtime.h>

#define HH 512
#define WW 512
#define BATCH 2
#define C2 64
#define MH 504
#define N1 168
#define N2 56
#define N3 19
#define N4 7
#define N5 3

// scratch (device globals: allocation-free per harness rules)
__device__ unsigned char g_mode[BATCH*3*MH*MH];
__device__ float g_d1[BATCH*C2*N1*N1];
__device__ float g_d2[BATCH*C2*N2*N2];
__device__ float g_d3[BATCH*C2*N3*N3];
__device__ float g_d4[BATCH*C2*N4*N4];
__device__ float g_d5[BATCH*C2*N5*N5];
__device__ float g_sA[(size_t)BATCH*C2*HH*WW];
__device__ float g_sB[(size_t)BATCH*C2*HH*WW];

// ---------------------------------------------------------------------------
// K1: ColorDownsample + ModePool2d(11, pad=1).  bin = rint(x*255/16) in 0..16,
// pad cells count as bin 0.  Output uint8 argmax bin per (b, ch, oy, ox).
// ---------------------------------------------------------------------------
__global__ void k_mode(const float* __restrict__ x) {
    __shared__ unsigned char sb[18][42];
    __shared__ unsigned short hist[17][256];
    int tx = threadIdx.x, ty = threadIdx.y;
    int t = ty * 32 + tx;
    int ox0 = blockIdx.x * 32, oy0 = blockIdx.y * 8;
    int bc = blockIdx.z;                       // b*3 + ch
    const float* xp = x + (size_t)bc * HH * WW;

    for (int i = t; i < 18 * 42; i += 256) {
        int r = i / 42, c = i - r * 42;
        int gy = oy0 - 1 + r, gx = ox0 - 1 + c;
        unsigned char v = 0;
        if (gy >= 0 && gy < HH && gx >= 0 && gx < WW) {
            int bi = (int)rintf(xp[(size_t)gy * WW + gx] * 255.0f / 16.0f);
            bi = bi < 0 ? 0 : (bi > 16 ? 16 : bi);
            v = (unsigned char)bi;
        }
        sb[r][c] = v;
    }
    __syncthreads();

    int ox = ox0 + tx, oy = oy0 + ty;
    if (ox >= MH || oy >= MH) return;

    #pragma unroll
    for (int b = 0; b < 17; b++) hist[b][t] = 0;
    for (int wy = 0; wy < 11; wy++) {
        #pragma unroll
        for (int wx = 0; wx < 11; wx++) {
            hist[sb[ty + wy][tx + wx]][t]++;
        }
    }
    int best = 0, bcnt = hist[0][t];
    #pragma unroll
    for (int b = 1; b < 17; b++) {
        int c = hist[b][t];
        if (c > bcnt) { bcnt = c; best = b; }
    }
    g_mode[((size_t)bc * MH + oy) * MH + ox] = (unsigned char)best;
}

// ---------------------------------------------------------------------------
// K2: fused conv1(1x1,3->64) + MaxLeaky + grouped conv2(1x1) + MinLeaky +
// first downgrade (shared 3x3, stride 3, pad 1) + leaky  ->  d1 [2,64,168,168]
// Each thread handles one spatial position for a channel PAIR (shares h0,h1).
// ---------------------------------------------------------------------------
__global__ void k_d1(const float* __restrict__ w1, const float* __restrict__ b1,
                     const float* __restrict__ w2, const float* __restrict__ b2,
                     const float* __restrict__ dk, const float* __restrict__ db) {
    __shared__ unsigned char sb[3][3][48];
    __shared__ float sdk[9];
    int tx = threadIdx.x;           // 0..15  -> xo
    int g  = threadIdx.y;           // 0..31  -> channel pair
    int t  = g * 16 + tx;
    int xo0 = blockIdx.x * 16;
    int yo  = blockIdx.y;
    int b   = blockIdx.z;
    if (t < 9) sdk[t] = dk[t];
    for (int i = t; i < 3 * 3 * 48; i += 512) {
        int ch = i / 144; int r = i - ch * 144; int ky = r / 48; int lx = r - ky * 48;
        int gy = 3 * yo - 1 + ky, gx = 3 * xo0 - 1 + lx;
        unsigned char v = 255;      // sentinel: conv zero-pad (term omitted)
        if (gy >= 0 && gy < MH && gx >= 0 && gx < MH)
            v = g_mode[(((size_t)b * 3 + ch) * MH + gy) * MH + gx];
        sb[ch][ky][lx] = v;
    }
    __syncthreads();
    int xo = xo0 + tx;
    if (xo >= N1) return;

    int c0 = 2 * g, c1 = c0 + 1;
    float w100 = w1[c0*3], w101 = w1[c0*3+1], w102 = w1[c0*3+2], bb10 = b1[c0];
    float w110 = w1[c1*3], w111 = w1[c1*3+1], w112 = w1[c1*3+2], bb11 = b1[c1];
    float w200 = w2[c0*2], w201 = w2[c0*2+1], bb20 = b2[c0];
    float w210 = w2[c1*2], w211 = w2[c1*2+1], bb21 = b2[c1];

    float acc0 = 0.f, acc1 = 0.f;
    #pragma unroll
    for (int ky = 0; ky < 3; ky++) {
        #pragma unroll
        for (int kx = 0; kx < 3; kx++) {
            int lx = 3 * tx + kx;
            unsigned char v0 = sb[0][ky][lx];
            if (v0 == 255) continue;
            float f0 = v0 * 0.0625f;
            float f1 = sb[1][ky][lx] * 0.0625f;
            float f2 = sb[2][ky][lx] * 0.0625f;
            float h0 = fmaf(w100, f0, fmaf(w101, f1, fmaf(w102, f2, bb10)));
            h0 = fminf(h0, fmaf(0.01f, h0 - 0.1f, 0.1f));       // MaxLeaky(0.1,0.01)
            float h1 = fmaf(w110, f0, fmaf(w111, f1, fmaf(w112, f2, bb11)));
            h1 = fminf(h1, fmaf(0.01f, h1 - 0.1f, 0.1f));
            float e0 = fmaf(w200, h0, fmaf(w201, h1, bb20));
            e0 = fmaxf(e0, fmaf(0.01f, e0 - 0.1f, 0.1f));        // MinLeaky(0.1,0.01)
            float e1 = fmaf(w210, h0, fmaf(w211, h1, bb21));
            e1 = fmaxf(e1, fmaf(0.01f, e1 - 0.1f, 0.1f));
            float kkv = sdk[ky * 3 + kx];
            acc0 = fmaf(kkv, e0, acc0);
            acc1 = fmaf(kkv, e1, acc1);
        }
    }
    float bias = db[0];
    float o0 = acc0 + bias; o0 = fmaxf(o0, 0.01f * o0);          // leaky
    float o1 = acc1 + bias; o1 = fmaxf(o1, 0.01f * o1);
    size_t base = (size_t)b * C2;
    g_d1[((base + c0) * N1 + yo) * N1 + xo] = o0;
    g_d1[((base + c1) * N1 + yo) * N1 + xo] = o1;
}

// ---------------------------------------------------------------------------
// K3: generic downgrade (shared 3x3, stride 3, pad 1) + leaky
// ---------------------------------------------------------------------------
__global__ void k_down(int level, const float* __restrict__ dk, const float* __restrict__ db) {
    int Hin, Hout; const float* in; float* out;
    switch (level) {
        case 2:  in = g_d1; out = g_d2; Hin = N1; Hout = N2; break;
        case 3:  in = g_d2; out = g_d3; Hin = N2; Hout = N3; break;
        case 4:  in = g_d3; out = g_d4; Hin = N3; Hout = N4; break;
        default: in = g_d4; out = g_d5; Hin = N4; Hout = N5; break;
    }
    int idx = blockIdx.x * blockDim.x + threadIdx.x;
    int total = BATCH * C2 * Hout * Hout;
    if (idx >= total) return;
    int xo = idx % Hout; int r = idx / Hout; int yo = r % Hout; int bc = r / Hout;
    const float* ip = in + (size_t)bc * Hin * Hin;
    float acc = db[0];
    #pragma unroll
    for (int ky = 0; ky < 3; ky++) {
        int yi = 3 * yo - 1 + ky;
        if (yi < 0 || yi >= Hin) continue;
        #pragma unroll
        for (int kx = 0; kx < 3; kx++) {
            int xi = 3 * xo - 1 + kx;
            if (xi < 0 || xi >= Hin) continue;
            acc = fmaf(dk[ky * 3 + kx], ip[(size_t)yi * Hin + xi], acc);
        }
    }
    out[idx] = fmaxf(acc, 0.01f * acc);
}

// ---------------------------------------------------------------------------
// K4: accumulate:  for each of 5 pyramid levels, bilinear-resize to 512x512
// (half-pixel, edge-clamped = jax.image.resize bilinear upsample), shared 5x5
// conv (zero pad 2) + BN + leaky, summed.  Writes g_sA.
// Tile 32x32 per (b,c); z tile (36x36) staged in smem per level.
// ---------------------------------------------------------------------------
__global__ void k_acc(const float* __restrict__ ik, const float* __restrict__ ib,
                      const float* __restrict__ ig, const float* __restrict__ ibt,
                      const float* __restrict__ im, const float* __restrict__ iv) {
    __shared__ float zs[36][37];
    __shared__ float kk[25];
    int tx = threadIdx.x, ty = threadIdx.y;
    int t = ty * 32 + tx;
    int x0 = blockIdx.x * 32, y0 = blockIdx.y * 32;
    int c = blockIdx.z & 63, b = blockIdx.z >> 6;
    if (t < 25) kk[t] = ik[t];
    float a   = ig[c] * rsqrtf(iv[c] + 1e-5f);
    float bc_ = ibt[c] - im[c] * a;
    float bias = ib[0];
    float acc[4] = {0.f, 0.f, 0.f, 0.f};

    for (int l = 0; l < 5; l++) {
        const float* dl; int n;
        switch (l) {
            case 0:  dl = g_d1; n = N1; break;
            case 1:  dl = g_d2; n = N2; break;
            case 2:  dl = g_d3; n = N3; break;
            case 3:  dl = g_d4; n = N4; break;
            default: dl = g_d5; n = N5; break;
        }
        dl += ((size_t)b * C2 + c) * n * n;
        float scale = n * (1.0f / 512.0f);
        __syncthreads();
        for (int i = t; i < 36 * 36; i += 256) {
            int sy = i / 36, sx = i - sy * 36;
            int gy = y0 - 2 + sy, gx = x0 - 2 + sx;
            float z = 0.f;
            if (gy >= 0 && gy < HH && gx >= 0 && gx < WW) {
                float fsy = fminf(fmaxf((gy + 0.5f) * scale - 0.5f, 0.f), (float)(n - 1));
                float fsx = fminf(fmaxf((gx + 0.5f) * scale - 0.5f, 0.f), (float)(n - 1));
                int iy0 = (int)fsy; float fy = fsy - iy0; int iy1 = iy0 + 1 < n ? iy0 + 1 : n - 1;
                int ix0 = (int)fsx; float fx = fsx - ix0; int ix1 = ix0 + 1 < n ? ix0 + 1 : n - 1;
                float v00 = dl[(size_t)iy0 * n + ix0], v01 = dl[(size_t)iy0 * n + ix1];
                float v10 = dl[(size_t)iy1 * n + ix0], v11 = dl[(size_t)iy1 * n + ix1];
                float top = v00 + fx * (v01 - v00);
                float bot = v10 + fx * (v11 - v10);
                z = top + fy * (bot - top);
            }
            zs[sy][sx] = z;
        }
        __syncthreads();
        #pragma unroll
        for (int i = 0; i < 4; i++) {
            int ly = ty + 8 * i;
            float s = bias;
            #pragma unroll
            for (int j = 0; j < 5; j++)
                #pragma unroll
                for (int i2 = 0; i2 < 5; i2++)
                    s = fmaf(kk[j * 5 + i2], zs[ly + j][tx + i2], s);
            float v = fmaf(a, s, bc_);
            acc[i] += fmaxf(v, 0.01f * v);
        }
    }
    size_t base = (((size_t)b * C2 + c) * HH + y0) * WW + x0;
    #pragma unroll
    for (int i = 0; i < 4; i++)
        g_sA[base + (size_t)(ty + 8 * i) * WW + tx] = acc[i];
}

// ---------------------------------------------------------------------------
// K5: one "ft" iteration:  s = A_c*score + B_c (BN folded with scalar 1x1),
// out = s + w_c*(s - boxsum11x11(s)/121)   (zero-padded SAME box).
// Tiled 32x32, separable box sum in smem.
// ---------------------------------------------------------------------------
__global__ void k_ft(int mode, float* __restrict__ outbuf,
                     const float* __restrict__ fg, const float* __restrict__ fb,
                     const float* __restrict__ fm, const float* __restrict__ fv,
                     const float* __restrict__ fk, const float* __restrict__ fbb,
                     const float* __restrict__ ew) {
    __shared__ float ss[42][43];
    __shared__ float rs[42][32];
    int tx = threadIdx.x, ty = threadIdx.y;
    int t = ty * 32 + tx;
    int x0 = blockIdx.x * 32, y0 = blockIdx.y * 32;
    int c = blockIdx.z & 63, b = blockIdx.z >> 6;

    const float* in; float* o;
    if (mode == 0)      { in = g_sA; o = g_sB; }
    else if (mode == 1) { in = g_sB; o = g_sA; }
    else                { in = g_sA; o = outbuf; }

    float gs = fg[c] * rsqrtf(fv[c] + 1e-5f);
    float k0 = fk[0];
    float A  = k0 * gs;
    float Bc = fmaf(k0, fb[c] - fm[c] * gs, fbb[0]);
    float w  = ew[c];

    const float* ip = in + ((size_t)b * C2 + c) * HH * WW;
    for (int i = t; i < 42 * 42; i += 256) {
        int sy = i / 42, sx = i - sy * 42;
        int gy = y0 - 5 + sy, gx = x0 - 5 + sx;
        float v = 0.f;
        if (gy >= 0 && gy < HH && gx >= 0 && gx < WW)
            v = fmaf(A, ip[(size_t)gy * WW + gx], Bc);
        ss[sy][sx] = v;
    }
    __syncthreads();
    for (int i = t; i < 42 * 32; i += 256) {
        int r = i / 32, cc = i - r * 32;
        float s = 0.f;
        #pragma unroll
        for (int dx = 0; dx < 11; dx++) s += ss[r][cc + dx];
        rs[r][cc] = s;
    }
    __syncthreads();
    float* op = o + ((size_t)b * C2 + c) * HH * WW + (size_t)y0 * WW + x0;
    #pragma unroll
    for (int i = 0; i < 4; i++) {
        int ly = ty + 8 * i;
        float col = 0.f;
        #pragma unroll
        for (int dy = 0; dy < 11; dy++) col += rs[ly + dy][tx];
        float sv = ss[ly + 5][tx + 5];
        float avg = col / 121.0f;
        op[(size_t)ly * WW + tx] = fmaf(w, sv - avg, sv);
    }
}

// ---------------------------------------------------------------------------
extern "C" void kernel_launch(void* const* d_in, const int* in_sizes, int n_in,
                              void* d_out, int out_size) {
    const float* x        = (const float*)d_in[0];
    const float* w1       = (const float*)d_in[1];
    const float* b1       = (const float*)d_in[2];
    const float* w2       = (const float*)d_in[3];
    const float* b2       = (const float*)d_in[4];
    const float* down_k   = (const float*)d_in[5];
    const float* down_b   = (const float*)d_in[6];
    const float* ft_gamma = (const float*)d_in[7];
    const float* ft_beta  = (const float*)d_in[8];
    const float* ft_mean  = (const float*)d_in[9];
    const float* ft_var   = (const float*)d_in[10];
    const float* ft_k     = (const float*)d_in[11];
    const float* ft_b     = (const float*)d_in[12];
    const float* emph_w   = (const float*)d_in[13];
    const float* interp_k = (const float*)d_in[14];
    const float* interp_b = (const float*)d_in[15];
    const float* i_gamma  = (const float*)d_in[16];
    const float* i_beta   = (const float*)d_in[17];
    const float* i_mean   = (const float*)d_in[18];
    const float* i_var    = (const float*)d_in[19];
    float* out = (float*)d_out;

    k_mode<<<dim3(16, 63, 6), dim3(32, 8)>>>(x);
    k_d1<<<dim3(11, N1, 2), dim3(16, 32)>>>(w1, b1, w2, b2, down_k, down_b);
    k_down<<<(BATCH * C2 * N2 * N2 + 255) / 256, 256>>>(2, down_k, down_b);
    k_down<<<(BATCH * C2 * N3 * N3 + 255) / 256, 256>>>(3, down_k, down_b);
    k_down<<<(BATCH * C2 * N4 * N4 + 255) / 256, 256>>>(4, down_k, down_b);
    k_down<<<(BATCH * C2 * N5 * N5 + 255) / 256, 256>>>(5, down_k, down_b);
    k_acc<<<dim3(16, 16, 128), dim3(32, 8)>>>(interp_k, interp_b, i_gamma, i_beta, i_mean, i_var);
    k_ft<<<dim3(16, 16, 128), dim3(32, 8)>>>(0, out, ft_gamma, ft_beta, ft_mean, ft_var, ft_k, ft_b, emph_w);
    k_ft<<<dim3(16, 16, 128), dim3(32, 8)>>>(1, out, ft_gamma, ft_beta, ft_mean, ft_var, ft_k, ft_b, emph_w);
    k_ft<<<dim3(16, 16, 128), dim3(32, 8)>>>(2, out, ft_gamma, ft_beta, ft_mean, ft_var, ft_k, ft_b, emph_w);
}

// round 3
// speedup vs baseline: 1.4995x; 1.4995x over previous
#include <cuda_runtime.h>

#define HH 512
#define WW 512
#define BATCH 2
#define C2 64
#define MH 504
#define N1 168
#define N2 56
#define N3 19
#define N4 7
#define N5 3

typedef unsigned long long ull;

// scratch (device globals: allocation-free per harness rules)
__device__ unsigned char g_bins[BATCH*3*HH*WW];
__device__ unsigned char g_mode[BATCH*3*MH*MH];
__device__ float g_d1[BATCH*C2*N1*N1];
__device__ float g_d2[BATCH*C2*N2*N2];
__device__ float g_d3[BATCH*C2*N3*N3];
__device__ float g_d4[BATCH*C2*N4*N4];
__device__ float g_d5[BATCH*C2*N5*N5];
__device__ float g_sA[(size_t)BATCH*C2*HH*WW];
__device__ float g_sB[(size_t)BATCH*C2*HH*WW];

// ---- packed f32x2 helpers ------------------------------------------------
__device__ __forceinline__ ull pk(float lo, float hi) {
    ull r; asm("mov.b64 %0, {%1, %2};" : "=l"(r) : "f"(lo), "f"(hi)); return r;
}
__device__ __forceinline__ void upk(ull v, float& lo, float& hi) {
    asm("mov.b64 {%0, %1}, %2;" : "=f"(lo), "=f"(hi) : "l"(v));
}
__device__ __forceinline__ ull fma2(ull a, ull b, ull c) {
    ull d; asm("fma.rn.f32x2 %0, %1, %2, %3;" : "=l"(d) : "l"(a), "l"(b), "l"(c)); return d;
}
__device__ __forceinline__ ull add2(ull a, ull b) {
    ull d; asm("add.rn.f32x2 %0, %1, %2;" : "=l"(d) : "l"(a), "l"(b)); return d;
}
__device__ __forceinline__ ull mul2(ull a, ull b) {
    ull d; asm("mul.rn.f32x2 %0, %1, %2;" : "=l"(d) : "l"(a), "l"(b)); return d;
}
#define SGNMASK 0x8000000080000000ULL

// ---------------------------------------------------------------------------
// K0: quantize input to bins (0..16), bytes.
// ---------------------------------------------------------------------------
__global__ void k_bins(const float* __restrict__ x) {
    int i = blockIdx.x * blockDim.x + threadIdx.x;
    const int total4 = BATCH * 3 * HH * WW / 4;
    if (i >= total4) return;
    float4 v = ((const float4*)x)[i];
    uchar4 o;
    int b0 = (int)rintf(v.x * (255.0f/16.0f)); o.x = (unsigned char)(b0<0?0:(b0>16?16:b0));
    int b1 = (int)rintf(v.y * (255.0f/16.0f)); o.y = (unsigned char)(b1<0?0:(b1>16?16:b1));
    int b2 = (int)rintf(v.z * (255.0f/16.0f)); o.z = (unsigned char)(b2<0?0:(b2>16?16:b2));
    int b3 = (int)rintf(v.w * (255.0f/16.0f)); o.w = (unsigned char)(b3<0?0:(b3>16?16:b3));
    ((uchar4*)g_bins)[i] = o;
}

// ---------------------------------------------------------------------------
// K1: ModePool2d(11, pad=1) via y-sliding packed-register histogram.
// 17 bins x 8-bit counters in 3 u64 registers; +11/-11 updates per step.
// ---------------------------------------------------------------------------
#define MCHUNK 28
__global__ void k_mode(void) {
    __shared__ unsigned char srow[12][144];
    int tx = threadIdx.x;               // 0..127 -> column
    int bx = blockIdx.x, by = blockIdx.y, bc = blockIdx.z;
    int ox = bx * 128 + tx;
    int oy0 = by * MCHUNK;
    const unsigned char* bp = g_bins + (size_t)bc * HH * WW;
    int colbase = bx * 128 - 1;

    ull w0 = 0, w1 = 0, w2 = 0;

    auto stage = [&](int r) {
        int s = (r + 12) % 12;
        for (int j = tx; j < 138; j += 128) {
            int gx = colbase + j;
            unsigned char v = 0;
            if (r >= 0 && r < HH && gx >= 0 && gx < WW) v = bp[(size_t)r * WW + gx];
            srow[s][j] = v;
        }
    };
    auto addRow = [&](int r) {
        int s = (r + 12) % 12;
        #pragma unroll
        for (int d = 0; d < 11; d++) {
            int bv = srow[s][tx + d];
            ull one = 1ULL << ((bv & 7) << 3);
            if (bv < 8) w0 += one;
            else if (bv < 16) w1 += one;
            else w2 += 1ULL;
        }
    };
    auto subRow = [&](int r) {
        int s = (r + 12) % 12;
        #pragma unroll
        for (int d = 0; d < 11; d++) {
            int bv = srow[s][tx + d];
            ull one = 1ULL << ((bv & 7) << 3);
            if (bv < 8) w0 -= one;
            else if (bv < 16) w1 -= one;
            else w2 -= 1ULL;
        }
    };

    for (int r = oy0 - 1; r <= oy0 + 9; r++) stage(r);
    __syncthreads();
    for (int r = oy0 - 1; r <= oy0 + 9; r++) addRow(r);

    for (int k = 0; k < MCHUNK; k++) {
        int oy = oy0 + k;
        // argmax, first-max wins ties
        int best = 0, bcnt = (int)(w0 & 0xFF);
        #pragma unroll
        for (int b = 1; b < 8; b++) {
            int c = (int)((w0 >> (b * 8)) & 0xFF);
            if (c > bcnt) { bcnt = c; best = b; }
        }
        #pragma unroll
        for (int b = 0; b < 8; b++) {
            int c = (int)((w1 >> (b * 8)) & 0xFF);
            if (c > bcnt) { bcnt = c; best = b + 8; }
        }
        { int c = (int)(w2 & 0xFF); if (c > bcnt) { bcnt = c; best = 16; } }
        if (ox < MH) g_mode[((size_t)bc * MH + oy) * MH + ox] = (unsigned char)best;

        if (k + 1 < MCHUNK) {
            int radd = oy + 10;
            __syncthreads();          // prior reads of slot being overwritten done
            stage(radd);
            __syncthreads();
            addRow(radd);
            subRow(oy - 1);
        }
    }
}

// ---------------------------------------------------------------------------
// K2: fused conv1(1x1,3->64)+MaxLeaky+grouped conv2(1x1)+MinLeaky+
// downgrade1 (shared 3x3 s3 p1) + leaky  ->  d1
// ---------------------------------------------------------------------------
__global__ void k_d1(const float* __restrict__ w1, const float* __restrict__ b1,
                     const float* __restrict__ w2, const float* __restrict__ b2,
                     const float* __restrict__ dk, const float* __restrict__ db) {
    __shared__ unsigned char sb[3][3][48];
    __shared__ float sdk[9];
    int tx = threadIdx.x;
    int g  = threadIdx.y;
    int t  = g * 16 + tx;
    int xo0 = blockIdx.x * 16;
    int yo  = blockIdx.y;
    int b   = blockIdx.z;
    if (t < 9) sdk[t] = dk[t];
    for (int i = t; i < 3 * 3 * 48; i += 512) {
        int ch = i / 144; int r = i - ch * 144; int ky = r / 48; int lx = r - ky * 48;
        int gy = 3 * yo - 1 + ky, gx = 3 * xo0 - 1 + lx;
        unsigned char v = 255;
        if (gy >= 0 && gy < MH && gx >= 0 && gx < MH)
            v = g_mode[(((size_t)b * 3 + ch) * MH + gy) * MH + gx];
        sb[ch][ky][lx] = v;
    }
    __syncthreads();
    int xo = xo0 + tx;
    if (xo >= N1) return;

    int c0 = 2 * g, c1 = c0 + 1;
    float w100 = w1[c0*3], w101 = w1[c0*3+1], w102 = w1[c0*3+2], bb10 = b1[c0];
    float w110 = w1[c1*3], w111 = w1[c1*3+1], w112 = w1[c1*3+2], bb11 = b1[c1];
    float w200 = w2[c0*2], w201 = w2[c0*2+1], bb20 = b2[c0];
    float w210 = w2[c1*2], w211 = w2[c1*2+1], bb21 = b2[c1];

    float acc0 = 0.f, acc1 = 0.f;
    #pragma unroll
    for (int ky = 0; ky < 3; ky++) {
        #pragma unroll
        for (int kx = 0; kx < 3; kx++) {
            int lx = 3 * tx + kx;
            unsigned char v0 = sb[0][ky][lx];
            if (v0 == 255) continue;
            float f0 = v0 * 0.0625f;
            float f1 = sb[1][ky][lx] * 0.0625f;
            float f2 = sb[2][ky][lx] * 0.0625f;
            float h0 = fmaf(w100, f0, fmaf(w101, f1, fmaf(w102, f2, bb10)));
            h0 = fminf(h0, fmaf(0.01f, h0 - 0.1f, 0.1f));
            float h1 = fmaf(w110, f0, fmaf(w111, f1, fmaf(w112, f2, bb11)));
            h1 = fminf(h1, fmaf(0.01f, h1 - 0.1f, 0.1f));
            float e0 = fmaf(w200, h0, fmaf(w201, h1, bb20));
            e0 = fmaxf(e0, fmaf(0.01f, e0 - 0.1f, 0.1f));
            float e1 = fmaf(w210, h0, fmaf(w211, h1, bb21));
            e1 = fmaxf(e1, fmaf(0.01f, e1 - 0.1f, 0.1f));
            float kkv = sdk[ky * 3 + kx];
            acc0 = fmaf(kkv, e0, acc0);
            acc1 = fmaf(kkv, e1, acc1);
        }
    }
    float bias = db[0];
    float o0 = acc0 + bias; o0 = fmaxf(o0, 0.01f * o0);
    float o1 = acc1 + bias; o1 = fmaxf(o1, 0.01f * o1);
    size_t base = (size_t)b * C2;
    g_d1[((base + c0) * N1 + yo) * N1 + xo] = o0;
    g_d1[((base + c1) * N1 + yo) * N1 + xo] = o1;
}

// ---------------------------------------------------------------------------
// K3: generic downgrade (shared 3x3, stride 3, pad 1) + leaky
// ---------------------------------------------------------------------------
__global__ void k_down(int level, const float* __restrict__ dk, const float* __restrict__ db) {
    int Hin, Hout; const float* in; float* out;
    switch (level) {
        case 2:  in = g_d1; out = g_d2; Hin = N1; Hout = N2; break;
        case 3:  in = g_d2; out = g_d3; Hin = N2; Hout = N3; break;
        case 4:  in = g_d3; out = g_d4; Hin = N3; Hout = N4; break;
        default: in = g_d4; out = g_d5; Hin = N4; Hout = N5; break;
    }
    int idx = blockIdx.x * blockDim.x + threadIdx.x;
    int total = BATCH * C2 * Hout * Hout;
    if (idx >= total) return;
    int xo = idx % Hout; int r = idx / Hout; int yo = r % Hout; int bc = r / Hout;
    const float* ip = in + (size_t)bc * Hin * Hin;
    float acc = db[0];
    #pragma unroll
    for (int ky = 0; ky < 3; ky++) {
        int yi = 3 * yo - 1 + ky;
        if (yi < 0 || yi >= Hin) continue;
        #pragma unroll
        for (int kx = 0; kx < 3; kx++) {
            int xi = 3 * xo - 1 + kx;
            if (xi < 0 || xi >= Hin) continue;
            acc = fmaf(dk[ky * 3 + kx], ip[(size_t)yi * Hin + xi], acc);
        }
    }
    out[idx] = fmaxf(acc, 0.01f * acc);
}

// ---------------------------------------------------------------------------
// K4: accumulate (bilinear up + shared 5x5 conv + BN + leaky, 5 levels).
// Channel-PAIR packed f32x2; each thread does 4 consecutive y rows with
// row-register reuse (5 LDS.64 per staged row feed all 5 kernel rows).
// ---------------------------------------------------------------------------
__global__ void __launch_bounds__(256) k_acc(
        const float* __restrict__ ik, const float* __restrict__ ib,
        const float* __restrict__ ig, const float* __restrict__ ibt,
        const float* __restrict__ im, const float* __restrict__ iv) {
    __shared__ ull zs[36][37];
    int tx = threadIdx.x, ty = threadIdx.y;
    int t = ty * 32 + tx;
    int x0 = blockIdx.x * 32, y0 = blockIdx.y * 32;
    int cp = blockIdx.z & 31, b = blockIdx.z >> 5;
    int c0 = cp * 2;

    ull kr[25];
    #pragma unroll
    for (int i = 0; i < 25; i++) { float kv = ik[i]; kr[i] = pk(kv, kv); }

    float a0 = ig[c0]   * rsqrtf(iv[c0]   + 1e-5f);
    float a1 = ig[c0+1] * rsqrtf(iv[c0+1] + 1e-5f);
    float bc0 = ibt[c0]   - im[c0]   * a0;
    float bc1 = ibt[c0+1] - im[c0+1] * a1;
    ull a2 = pk(a0, a1), bn2 = pk(bc0, bc1);
    float bias = ib[0];
    ull bias2 = pk(bias, bias);

    float accL[4] = {0.f,0.f,0.f,0.f}, accH[4] = {0.f,0.f,0.f,0.f};
    int zr0 = ty * 4;

    for (int l = 0; l < 5; l++) {
        const float* dl; int n;
        switch (l) {
            case 0:  dl = g_d1; n = N1; break;
            case 1:  dl = g_d2; n = N2; break;
            case 2:  dl = g_d3; n = N3; break;
            case 3:  dl = g_d4; n = N4; break;
            default: dl = g_d5; n = N5; break;
        }
        const float* dl0 = dl + ((size_t)b * C2 + c0) * n * n;
        const float* dl1 = dl0 + (size_t)n * n;
        float scale = n * (1.0f / 512.0f);
        __syncthreads();
        for (int i = t; i < 36 * 36; i += 256) {
            int sy = i / 36, sx = i - sy * 36;
            int gy = y0 - 2 + sy, gx = x0 - 2 + sx;
            float z0 = 0.f, z1 = 0.f;
            if (gy >= 0 && gy < HH && gx >= 0 && gx < WW) {
                float fsy = fminf(fmaxf((gy + 0.5f) * scale - 0.5f, 0.f), (float)(n - 1));
                float fsx = fminf(fmaxf((gx + 0.5f) * scale - 0.5f, 0.f), (float)(n - 1));
                int iy0 = (int)fsy; float fy = fsy - iy0; int iy1 = iy0 + 1 < n ? iy0 + 1 : n - 1;
                int ix0 = (int)fsx; float fx = fsx - ix0; int ix1 = ix0 + 1 < n ? ix0 + 1 : n - 1;
                size_t o00 = (size_t)iy0 * n + ix0, o01 = (size_t)iy0 * n + ix1;
                size_t o10 = (size_t)iy1 * n + ix0, o11 = (size_t)iy1 * n + ix1;
                {
                    float v00 = dl0[o00], v01 = dl0[o01], v10 = dl0[o10], v11 = dl0[o11];
                    float top = v00 + fx * (v01 - v00);
                    float bot = v10 + fx * (v11 - v10);
                    z0 = top + fy * (bot - top);
                }
                {
                    float v00 = dl1[o00], v01 = dl1[o01], v10 = dl1[o10], v11 = dl1[o11];
                    float top = v00 + fx * (v01 - v00);
                    float bot = v10 + fx * (v11 - v10);
                    z1 = top + fy * (bot - top);
                }
            }
            zs[sy][sx] = pk(z0, z1);
        }
        __syncthreads();

        ull s[4] = {bias2, bias2, bias2, bias2};
        #pragma unroll
        for (int r = 0; r < 8; r++) {
            ull v0 = zs[zr0 + r][tx + 0];
            ull v1 = zs[zr0 + r][tx + 1];
            ull v2 = zs[zr0 + r][tx + 2];
            ull v3 = zs[zr0 + r][tx + 3];
            ull v4 = zs[zr0 + r][tx + 4];
            #pragma unroll
            for (int j = 0; j < 5; j++) {
                int q = r - j;
                if (q >= 0 && q < 4) {
                    s[q] = fma2(kr[j*5+0], v0, s[q]);
                    s[q] = fma2(kr[j*5+1], v1, s[q]);
                    s[q] = fma2(kr[j*5+2], v2, s[q]);
                    s[q] = fma2(kr[j*5+3], v3, s[q]);
                    s[q] = fma2(kr[j*5+4], v4, s[q]);
                }
            }
        }
        #pragma unroll
        for (int q = 0; q < 4; q++) {
            ull v = fma2(a2, s[q], bn2);
            float lo, hi; upk(v, lo, hi);
            accL[q] += fmaxf(lo, 0.01f * lo);
            accH[q] += fmaxf(hi, 0.01f * hi);
        }
    }
    size_t base0 = (((size_t)b * C2 + c0) * HH + y0 + zr0) * WW + x0 + tx;
    size_t base1 = base0 + (size_t)HH * WW;
    #pragma unroll
    for (int q = 0; q < 4; q++) {
        g_sA[base0 + (size_t)q * WW] = accL[q];
        g_sA[base1 + (size_t)q * WW] = accH[q];
    }
}

// ---------------------------------------------------------------------------
// K5: ft iteration, channel-pair packed, sliding-window box sums.
// out = s + w*(s - boxsum11(s)/121), s = A*score + B.
// ---------------------------------------------------------------------------
__global__ void __launch_bounds__(256) k_ft(int mode, float* __restrict__ outbuf,
                     const float* __restrict__ fg, const float* __restrict__ fb,
                     const float* __restrict__ fm, const float* __restrict__ fv,
                     const float* __restrict__ fk, const float* __restrict__ fbb,
                     const float* __restrict__ ew) {
    __shared__ ull ss[42][43];
    __shared__ ull rs[42][33];
    int tx = threadIdx.x, ty = threadIdx.y;
    int t = ty * 32 + tx;
    int x0 = blockIdx.x * 32, y0 = blockIdx.y * 32;
    int cp = blockIdx.z & 31, b = blockIdx.z >> 5;
    int c0 = cp * 2;

    const float* in; float* o;
    if (mode == 0)      { in = g_sA; o = g_sB; }
    else if (mode == 1) { in = g_sB; o = g_sA; }
    else                { in = g_sA; o = outbuf; }

    float k0 = fk[0];
    float gs0 = fg[c0]   * rsqrtf(fv[c0]   + 1e-5f);
    float gs1 = fg[c0+1] * rsqrtf(fv[c0+1] + 1e-5f);
    float A0 = k0 * gs0, B0 = fmaf(k0, fb[c0]   - fm[c0]   * gs0, fbb[0]);
    float A1 = k0 * gs1, B1 = fmaf(k0, fb[c0+1] - fm[c0+1] * gs1, fbb[0]);
    ull w2v = pk(ew[c0], ew[c0+1]);
    ull c121 = pk(1.0f/121.0f, 1.0f/121.0f);

    const float* ip0 = in + ((size_t)b * C2 + c0) * HH * WW;
    const float* ip1 = ip0 + (size_t)HH * WW;
    for (int i = t; i < 42 * 42; i += 256) {
        int sy = i / 42, sx = i - sy * 42;
        int gy = y0 - 5 + sy, gx = x0 - 5 + sx;
        float v0 = 0.f, v1 = 0.f;
        if (gy >= 0 && gy < HH && gx >= 0 && gx < WW) {
            size_t off = (size_t)gy * WW + gx;
            v0 = fmaf(A0, ip0[off], B0);
            v1 = fmaf(A1, ip1[off], B1);
        }
        ss[sy][sx] = pk(v0, v1);
    }
    __syncthreads();

    // row sums: 4 consecutive columns per task, sliding
    for (int i = t; i < 42 * 8; i += 256) {
        int r = i >> 3, cc = (i & 7) * 4;
        ull v[14];
        #pragma unroll
        for (int d = 0; d < 14; d++) v[d] = ss[r][cc + d];
        ull s = v[0];
        #pragma unroll
        for (int d = 1; d < 11; d++) s = add2(s, v[d]);
        rs[r][cc] = s;
        s = add2(add2(s, v[0] ^ SGNMASK), v[11]);  rs[r][cc + 1] = s;
        s = add2(add2(s, v[1] ^ SGNMASK), v[12]);  rs[r][cc + 2] = s;
        s = add2(add2(s, v[2] ^ SGNMASK), v[13]);  rs[r][cc + 3] = s;
    }
    __syncthreads();

    // column sums: 4 consecutive rows per thread, sliding
    int yl0 = ty * 4;
    ull cv[14];
    #pragma unroll
    for (int d = 0; d < 14; d++) cv[d] = rs[yl0 + d][tx];
    ull col = cv[0];
    #pragma unroll
    for (int d = 1; d < 11; d++) col = add2(col, cv[d]);

    float* op0 = o + (((size_t)b * C2 + c0) * HH + y0 + yl0) * WW + x0 + tx;
    float* op1 = op0 + (size_t)HH * WW;
    #pragma unroll
    for (int q = 0; q < 4; q++) {
        if (q > 0) col = add2(add2(col, cv[q - 1] ^ SGNMASK), cv[q + 10]);
        ull sv = ss[yl0 + q + 5][tx + 5];
        ull avg = mul2(col, c121);
        ull diff = add2(sv, avg ^ SGNMASK);
        ull ov = fma2(w2v, diff, sv);
        float lo, hi; upk(ov, lo, hi);
        op0[(size_t)q * WW] = lo;
        op1[(size_t)q * WW] = hi;
    }
}

// ---------------------------------------------------------------------------
extern "C" void kernel_launch(void* const* d_in, const int* in_sizes, int n_in,
                              void* d_out, int out_size) {
    const float* x        = (const float*)d_in[0];
    const float* w1       = (const float*)d_in[1];
    const float* b1       = (const float*)d_in[2];
    const float* w2       = (const float*)d_in[3];
    const float* b2       = (const float*)d_in[4];
    const float* down_k   = (const float*)d_in[5];
    const float* down_b   = (const float*)d_in[6];
    const float* ft_gamma = (const float*)d_in[7];
    const float* ft_beta  = (const float*)d_in[8];
    const float* ft_mean  = (const float*)d_in[9];
    const float* ft_var   = (const float*)d_in[10];
    const float* ft_k     = (const float*)d_in[11];
    const float* ft_b     = (const float*)d_in[12];
    const float* emph_w   = (const float*)d_in[13];
    const float* interp_k = (const float*)d_in[14];
    const float* interp_b = (const float*)d_in[15];
    const float* i_gamma  = (const float*)d_in[16];
    const float* i_beta   = (const float*)d_in[17];
    const float* i_mean   = (const float*)d_in[18];
    const float* i_var    = (const float*)d_in[19];
    float* out = (float*)d_out;

    k_bins<<<(BATCH*3*HH*WW/4 + 255)/256, 256>>>(x);
    k_mode<<<dim3(4, 18, 6), 128>>>();
    k_d1<<<dim3(11, N1, 2), dim3(16, 32)>>>(w1, b1, w2, b2, down_k, down_b);
    k_down<<<(BATCH * C2 * N2 * N2 + 255) / 256, 256>>>(2, down_k, down_b);
    k_down<<<(BATCH * C2 * N3 * N3 + 255) / 256, 256>>>(3, down_k, down_b);
    k_down<<<(BATCH * C2 * N4 * N4 + 255) / 256, 256>>>(4, down_k, down_b);
    k_down<<<(BATCH * C2 * N5 * N5 + 255) / 256, 256>>>(5, down_k, down_b);
    k_acc<<<dim3(16, 16, 64), dim3(32, 8)>>>(interp_k, interp_b, i_gamma, i_beta, i_mean, i_var);
    k_ft<<<dim3(16, 16, 64), dim3(32, 8)>>>(0, out, ft_gamma, ft_beta, ft_mean, ft_var, ft_k, ft_b, emph_w);
    k_ft<<<dim3(16, 16, 64), dim3(32, 8)>>>(1, out, ft_gamma, ft_beta, ft_mean, ft_var, ft_k, ft_b, emph_w);
    k_ft<<<dim3(16, 16, 64), dim3(32, 8)>>>(2, out, ft_gamma, ft_beta, ft_mean, ft_var, ft_k, ft_b, emph_w);
}

// round 5
// speedup vs baseline: 1.5289x; 1.0196x over previous
#include <cuda_runtime.h>

#define HH 512
#define WW 512
#define BATCH 2
#define C2 64
#define MH 504
#define N1 168
#define N2 56
#define N3 19
#define N4 7
#define N5 3

typedef unsigned long long ull;

// scratch (device globals: allocation-free per harness rules)
__device__ unsigned char g_bins[BATCH*3*HH*WW];
__device__ unsigned char g_mode[BATCH*3*MH*MH];
__device__ float g_d1[BATCH*C2*N1*N1];
__device__ float g_d2[BATCH*C2*N2*N2];
__device__ float g_d3[BATCH*C2*N3*N3];
__device__ float g_d4[BATCH*C2*N4*N4];
__device__ float g_d5[BATCH*C2*N5*N5];
__device__ float g_sA[(size_t)BATCH*C2*HH*WW];

// ---- packed f32x2 helpers ------------------------------------------------
__device__ __forceinline__ ull pk(float lo, float hi) {
    ull r; asm("mov.b64 %0, {%1, %2};" : "=l"(r) : "f"(lo), "f"(hi)); return r;
}
__device__ __forceinline__ void upk(ull v, float& lo, float& hi) {
    asm("mov.b64 {%0, %1}, %2;" : "=f"(lo), "=f"(hi) : "l"(v));
}
__device__ __forceinline__ ull fma2(ull a, ull b, ull c) {
    ull d; asm("fma.rn.f32x2 %0, %1, %2, %3;" : "=l"(d) : "l"(a), "l"(b), "l"(c)); return d;
}
__device__ __forceinline__ ull add2(ull a, ull b) {
    ull d; asm("add.rn.f32x2 %0, %1, %2;" : "=l"(d) : "l"(a), "l"(b)); return d;
}
#define SGNMASK 0x8000000080000000ULL

// ---------------------------------------------------------------------------
// K0: quantize input to bins (0..16), bytes.
// ---------------------------------------------------------------------------
__global__ void k_bins(const float* __restrict__ x) {
    int i = blockIdx.x * blockDim.x + threadIdx.x;
    const int total4 = BATCH * 3 * HH * WW / 4;
    if (i >= total4) return;
    float4 v = ((const float4*)x)[i];
    uchar4 o;
    int b0 = (int)rintf(v.x * (255.0f/16.0f)); o.x = (unsigned char)(b0<0?0:(b0>16?16:b0));
    int b1 = (int)rintf(v.y * (255.0f/16.0f)); o.y = (unsigned char)(b1<0?0:(b1>16?16:b1));
    int b2 = (int)rintf(v.z * (255.0f/16.0f)); o.z = (unsigned char)(b2<0?0:(b2>16?16:b2));
    int b3 = (int)rintf(v.w * (255.0f/16.0f)); o.w = (unsigned char)(b3<0?0:(b3>16?16:b3));
    ((uchar4*)g_bins)[i] = o;
}

// ---------------------------------------------------------------------------
// K1: ModePool2d(11, pad=1) via y-sliding packed-register histogram.
// ---------------------------------------------------------------------------
#define MCHUNK 14
__global__ void k_mode(void) {
    __shared__ unsigned char srow[12][144];
    int tx = threadIdx.x;               // 0..127 -> column
    int bx = blockIdx.x, by = blockIdx.y, bc = blockIdx.z;
    int ox = bx * 128 + tx;
    int oy0 = by * MCHUNK;
    const unsigned char* bp = g_bins + (size_t)bc * HH * WW;
    int colbase = bx * 128 - 1;

    ull w0 = 0, w1 = 0, w2 = 0;

    auto stage = [&](int r) {
        int s = (r + 12) % 12;
        for (int j = tx; j < 138; j += 128) {
            int gx = colbase + j;
            unsigned char v = 0;
            if (r >= 0 && r < HH && gx >= 0 && gx < WW) v = bp[(size_t)r * WW + gx];
            srow[s][j] = v;
        }
    };
    auto addRow = [&](int r) {
        int s = (r + 12) % 12;
        #pragma unroll
        for (int d = 0; d < 11; d++) {
            int bv = srow[s][tx + d];
            ull one = 1ULL << ((bv & 7) << 3);
            if (bv < 8) w0 += one;
            else if (bv < 16) w1 += one;
            else w2 += 1ULL;
        }
    };
    auto subRow = [&](int r) {
        int s = (r + 12) % 12;
        #pragma unroll
        for (int d = 0; d < 11; d++) {
            int bv = srow[s][tx + d];
            ull one = 1ULL << ((bv & 7) << 3);
            if (bv < 8) w0 -= one;
            else if (bv < 16) w1 -= one;
            else w2 -= 1ULL;
        }
    };

    for (int r = oy0 - 1; r <= oy0 + 9; r++) stage(r);
    __syncthreads();
    for (int r = oy0 - 1; r <= oy0 + 9; r++) addRow(r);

    for (int k = 0; k < MCHUNK; k++) {
        int oy = oy0 + k;
        int best = 0, bcnt = (int)(w0 & 0xFF);
        #pragma unroll
        for (int b = 1; b < 8; b++) {
            int c = (int)((w0 >> (b * 8)) & 0xFF);
            if (c > bcnt) { bcnt = c; best = b; }
        }
        #pragma unroll
        for (int b = 0; b < 8; b++) {
            int c = (int)((w1 >> (b * 8)) & 0xFF);
            if (c > bcnt) { bcnt = c; best = b + 8; }
        }
        { int c = (int)(w2 & 0xFF); if (c > bcnt) { bcnt = c; best = 16; } }
        if (ox < MH) g_mode[((size_t)bc * MH + oy) * MH + ox] = (unsigned char)best;

        if (k + 1 < MCHUNK) {
            int radd = oy + 10;
            __syncthreads();
            stage(radd);
            __syncthreads();
            addRow(radd);
            subRow(oy - 1);
        }
    }
}

// ---------------------------------------------------------------------------
// K2: fused conv1 + MaxLeaky + grouped conv2 + MinLeaky + downgrade1 + leaky
// ---------------------------------------------------------------------------
__global__ void k_d1(const float* __restrict__ w1, const float* __restrict__ b1,
                     const float* __restrict__ w2, const float* __restrict__ b2,
                     const float* __restrict__ dk, const float* __restrict__ db) {
    __shared__ unsigned char sb[3][3][48];
    __shared__ float sdk[9];
    int tx = threadIdx.x;
    int g  = threadIdx.y;
    int t  = g * 16 + tx;
    int xo0 = blockIdx.x * 16;
    int yo  = blockIdx.y;
    int b   = blockIdx.z;
    if (t < 9) sdk[t] = dk[t];
    for (int i = t; i < 3 * 3 * 48; i += 512) {
        int ch = i / 144; int r = i - ch * 144; int ky = r / 48; int lx = r - ky * 48;
        int gy = 3 * yo - 1 + ky, gx = 3 * xo0 - 1 + lx;
        unsigned char v = 255;
        if (gy >= 0 && gy < MH && gx >= 0 && gx < MH)
            v = g_mode[(((size_t)b * 3 + ch) * MH + gy) * MH + gx];
        sb[ch][ky][lx] = v;
    }
    __syncthreads();
    int xo = xo0 + tx;
    if (xo >= N1) return;

    int c0 = 2 * g, c1 = c0 + 1;
    float w100 = w1[c0*3], w101 = w1[c0*3+1], w102 = w1[c0*3+2], bb10 = b1[c0];
    float w110 = w1[c1*3], w111 = w1[c1*3+1], w112 = w1[c1*3+2], bb11 = b1[c1];
    float w200 = w2[c0*2], w201 = w2[c0*2+1], bb20 = b2[c0];
    float w210 = w2[c1*2], w211 = w2[c1*2+1], bb21 = b2[c1];

    float acc0 = 0.f, acc1 = 0.f;
    #pragma unroll
    for (int ky = 0; ky < 3; ky++) {
        #pragma unroll
        for (int kx = 0; kx < 3; kx++) {
            int lx = 3 * tx + kx;
            unsigned char v0 = sb[0][ky][lx];
            if (v0 == 255) continue;
            float f0 = v0 * 0.0625f;
            float f1 = sb[1][ky][lx] * 0.0625f;
            float f2 = sb[2][ky][lx] * 0.0625f;
            float h0 = fmaf(w100, f0, fmaf(w101, f1, fmaf(w102, f2, bb10)));
            h0 = fminf(h0, fmaf(0.01f, h0 - 0.1f, 0.1f));
            float h1 = fmaf(w110, f0, fmaf(w111, f1, fmaf(w112, f2, bb11)));
            h1 = fminf(h1, fmaf(0.01f, h1 - 0.1f, 0.1f));
            float e0 = fmaf(w200, h0, fmaf(w201, h1, bb20));
            e0 = fmaxf(e0, fmaf(0.01f, e0 - 0.1f, 0.1f));
            float e1 = fmaf(w210, h0, fmaf(w211, h1, bb21));
            e1 = fmaxf(e1, fmaf(0.01f, e1 - 0.1f, 0.1f));
            float kkv = sdk[ky * 3 + kx];
            acc0 = fmaf(kkv, e0, acc0);
            acc1 = fmaf(kkv, e1, acc1);
        }
    }
    float bias = db[0];
    float o0 = acc0 + bias; o0 = fmaxf(o0, 0.01f * o0);
    float o1 = acc1 + bias; o1 = fmaxf(o1, 0.01f * o1);
    size_t base = (size_t)b * C2;
    g_d1[((base + c0) * N1 + yo) * N1 + xo] = o0;
    g_d1[((base + c1) * N1 + yo) * N1 + xo] = o1;
}

// ---------------------------------------------------------------------------
// K3: generic downgrade (shared 3x3, stride 3, pad 1) + leaky
// ---------------------------------------------------------------------------
__global__ void k_down(int level, const float* __restrict__ dk, const float* __restrict__ db) {
    int Hin, Hout; const float* in; float* out;
    switch (level) {
        case 2:  in = g_d1; out = g_d2; Hin = N1; Hout = N2; break;
        case 3:  in = g_d2; out = g_d3; Hin = N2; Hout = N3; break;
        case 4:  in = g_d3; out = g_d4; Hin = N3; Hout = N4; break;
        default: in = g_d4; out = g_d5; Hin = N4; Hout = N5; break;
    }
    int idx = blockIdx.x * blockDim.x + threadIdx.x;
    int total = BATCH * C2 * Hout * Hout;
    if (idx >= total) return;
    int xo = idx % Hout; int r = idx / Hout; int yo = r % Hout; int bc = r / Hout;
    const float* ip = in + (size_t)bc * Hin * Hin;
    float acc = db[0];
    #pragma unroll
    for (int ky = 0; ky < 3; ky++) {
        int yi = 3 * yo - 1 + ky;
        if (yi < 0 || yi >= Hin) continue;
        #pragma unroll
        for (int kx = 0; kx < 3; kx++) {
            int xi = 3 * xo - 1 + kx;
            if (xi < 0 || xi >= Hin) continue;
            acc = fmaf(dk[ky * 3 + kx], ip[(size_t)yi * Hin + xi], acc);
        }
    }
    out[idx] = fmaxf(acc, 0.01f * acc);
}

// ---------------------------------------------------------------------------
// K4: accumulate (bilinear up + shared 5x5 conv + BN + leaky, 5 levels).
// Separable two-pass bilinear staging (coarse strip -> fine), channel pairs.
// ---------------------------------------------------------------------------
__global__ void __launch_bounds__(256) k_acc(
        const float* __restrict__ ik, const float* __restrict__ ib,
        const float* __restrict__ ig, const float* __restrict__ ibt,
        const float* __restrict__ im, const float* __restrict__ iv) {
    __shared__ ull zs[36][37];
    __shared__ ull tmp[36][17];
    __shared__ int s_iy0[36], s_iy1[36];
    __shared__ float s_fy[36];
    __shared__ int s_jx0[36], s_jx1[36];
    __shared__ ull s_fx2[36];
    __shared__ unsigned char s_inbY[36], s_inbX[36];

    int tx = threadIdx.x, ty = threadIdx.y;
    int t = ty * 32 + tx;
    int x0 = blockIdx.x * 32, y0 = blockIdx.y * 32;
    int cp = blockIdx.z & 31, b = blockIdx.z >> 5;
    int c0 = cp * 2;

    ull kr[25];
    #pragma unroll
    for (int i = 0; i < 25; i++) { float kv = ik[i]; kr[i] = pk(kv, kv); }

    float a0 = ig[c0]   * rsqrtf(iv[c0]   + 1e-5f);
    float a1 = ig[c0+1] * rsqrtf(iv[c0+1] + 1e-5f);
    float bc0 = ibt[c0]   - im[c0]   * a0;
    float bc1 = ibt[c0+1] - im[c0+1] * a1;
    ull a2 = pk(a0, a1), bn2 = pk(bc0, bc1);
    float bias = ib[0];
    ull bias2 = pk(bias, bias);

    float accL[4] = {0.f,0.f,0.f,0.f}, accH[4] = {0.f,0.f,0.f,0.f};
    int zr0 = ty * 4;

    for (int l = 0; l < 5; l++) {
        const float* dl; int n;
        switch (l) {
            case 0:  dl = g_d1; n = N1; break;
            case 1:  dl = g_d2; n = N2; break;
            case 2:  dl = g_d3; n = N3; break;
            case 3:  dl = g_d4; n = N4; break;
            default: dl = g_d5; n = N5; break;
        }
        const float* dl0 = dl + ((size_t)b * C2 + c0) * n * n;
        const float* dl1 = dl0 + (size_t)n * n;
        float scale = n * (1.0f / 512.0f);
        float fsx0 = fminf(fmaxf((x0 - 1.5f) * scale - 0.5f, 0.f), (float)(n - 1));
        int cx0 = (int)fsx0;

        __syncthreads();
        if (t < 36) {
            int gy = y0 - 2 + t;
            s_inbY[t] = (gy >= 0 && gy < HH);
            float fsy = fminf(fmaxf((gy + 0.5f) * scale - 0.5f, 0.f), (float)(n - 1));
            int iy0 = (int)fsy; if (iy0 > n - 1) iy0 = n - 1;
            s_iy0[t] = iy0;
            s_iy1[t] = iy0 + 1 < n ? iy0 + 1 : n - 1;
            s_fy[t] = fsy - iy0;
            int gx = x0 - 2 + t;
            s_inbX[t] = (gx >= 0 && gx < WW);
            float fsx = fminf(fmaxf((gx + 0.5f) * scale - 0.5f, 0.f), (float)(n - 1));
            int ix0 = (int)fsx; if (ix0 > n - 1) ix0 = n - 1;
            s_jx0[t] = ix0;
            s_jx1[t] = ix0 + 1 < n ? ix0 + 1 : n - 1;
            float fx = fsx - ix0;
            s_fx2[t] = pk(fx, fx);
        }
        __syncthreads();
        for (int i = t; i < 36 * 16; i += 256) {
            int sy = i >> 4, j = i & 15;
            int cx = cx0 + j; if (cx > n - 1) cx = n - 1;
            int iy0 = s_iy0[sy], iy1 = s_iy1[sy]; float fy = s_fy[sy];
            float va0 = dl0[iy0 * n + cx], vb0 = dl0[iy1 * n + cx];
            float va1 = dl1[iy0 * n + cx], vb1 = dl1[iy1 * n + cx];
            tmp[sy][j] = pk(va0 + fy * (vb0 - va0), va1 + fy * (vb1 - va1));
        }
        __syncthreads();
        for (int i = t; i < 36 * 36; i += 256) {
            int sy = i / 36, sx = i - sy * 36;
            ull z = 0;
            if (s_inbY[sy] && s_inbX[sx]) {
                int j0 = s_jx0[sx] - cx0, j1 = s_jx1[sx] - cx0;
                ull v0 = tmp[sy][j0], v1 = tmp[sy][j1];
                ull d = add2(v1, v0 ^ SGNMASK);
                z = fma2(s_fx2[sx], d, v0);
            }
            zs[sy][sx] = z;
        }
        __syncthreads();

        ull s[4] = {bias2, bias2, bias2, bias2};
        #pragma unroll
        for (int r = 0; r < 8; r++) {
            ull v0 = zs[zr0 + r][tx + 0];
            ull v1 = zs[zr0 + r][tx + 1];
            ull v2 = zs[zr0 + r][tx + 2];
            ull v3 = zs[zr0 + r][tx + 3];
            ull v4 = zs[zr0 + r][tx + 4];
            #pragma unroll
            for (int j = 0; j < 5; j++) {
                int q = r - j;
                if (q >= 0 && q < 4) {
                    s[q] = fma2(kr[j*5+0], v0, s[q]);
                    s[q] = fma2(kr[j*5+1], v1, s[q]);
                    s[q] = fma2(kr[j*5+2], v2, s[q]);
                    s[q] = fma2(kr[j*5+3], v3, s[q]);
                    s[q] = fma2(kr[j*5+4], v4, s[q]);
                }
            }
        }
        #pragma unroll
        for (int q = 0; q < 4; q++) {
            ull v = fma2(a2, s[q], bn2);
            float lo, hi; upk(v, lo, hi);
            accL[q] += fmaxf(lo, 0.01f * lo);
            accH[q] += fmaxf(hi, 0.01f * hi);
        }
    }
    size_t base0 = (((size_t)b * C2 + c0) * HH + y0 + zr0) * WW + x0 + tx;
    size_t base1 = base0 + (size_t)HH * WW;
    #pragma unroll
    for (int q = 0; q < 4; q++) {
        g_sA[base0 + (size_t)q * WW] = accL[q];
        g_sA[base1 + (size_t)q * WW] = accH[q];
    }
}

// ---------------------------------------------------------------------------
// K5: ALL THREE ft iterations fused, in shared memory.
// Buffer BA always holds the CURRENT iteration's s-values (post-affine,
// zero OUTSIDE the image -> exact zero-pad box-sum semantics).  On write-back
// each iteration applies the next iteration's affine (iters 0,1) or leaves
// the raw emphase output (iter 2).
// ---------------------------------------------------------------------------
__global__ void __launch_bounds__(256) k_ft3(float* __restrict__ out,
                     const float* __restrict__ fg, const float* __restrict__ fb,
                     const float* __restrict__ fm, const float* __restrict__ fv,
                     const float* __restrict__ fk, const float* __restrict__ fbb,
                     const float* __restrict__ ew) {
    extern __shared__ float sm[];
    float* bufA = sm;                 // [94][95]
    float* bufB = sm + 94 * 95;       // [94][95]
    #define BA(r,c) bufA[(r)*95 + (c)]
    #define BB(r,c) bufB[(r)*95 + (c)]

    int t = threadIdx.x;
    int x0 = blockIdx.x * 64, y0 = blockIdx.y * 64;
    int c = blockIdx.z & 63, b = blockIdx.z >> 6;

    float k0 = fk[0];
    float gs = fg[c] * rsqrtf(fv[c] + 1e-5f);
    float A  = k0 * gs;
    float Bc = fmaf(k0, fb[c] - fm[c] * gs, fbb[0]);
    float w  = ew[c];

    // stage s = A*score + B (in image), 0 outside
    const float* ip = g_sA + ((size_t)b * C2 + c) * HH * WW;
    for (int i = t; i < 94 * 94; i += 256) {
        int r = i / 94, cc = i - r * 94;
        int gy = y0 - 15 + r, gx = x0 - 15 + cc;
        float v = 0.f;
        if ((unsigned)gy < HH && (unsigned)gx < WW)
            v = fmaf(A, ip[(size_t)gy * WW + gx], Bc);
        BA(r, cc) = v;
    }

    for (int it = 0; it < 3; it++) {
        int m = 5 * it;
        int C = 84 - 2 * m;
        int R = 94 - 2 * m;
        int G = (C + 3) >> 2;
        __syncthreads();
        // sliding row sums (4 cols per task)
        for (int i = t; i < R * G; i += 256) {
            int qd = i / G; int r = m + qd; int g = i - qd * G;
            int xg = m + 5 + g * 4;
            float v[14];
            #pragma unroll
            for (int d = 0; d < 14; d++) v[d] = BA(r, xg - 5 + d);
            float s = v[0];
            #pragma unroll
            for (int d = 1; d < 11; d++) s += v[d];
            BB(r, xg) = s;
            s += v[11] - v[0]; BB(r, xg + 1) = s;
            s += v[12] - v[1]; BB(r, xg + 2) = s;
            s += v[13] - v[2]; BB(r, xg + 3) = s;
        }
        __syncthreads();
        // sliding col sums + emphase + next-iteration affine, in place
        for (int i = t; i < C * G; i += 256) {
            int qd = i / G; int x = m + 5 + qd; int g = i - qd * G;
            int yg = m + 5 + g * 4;
            float cv[14];
            #pragma unroll
            for (int d = 0; d < 14; d++) cv[d] = BB(yg - 5 + d, x);
            float col = cv[0];
            #pragma unroll
            for (int d = 1; d < 11; d++) col += cv[d];
            #pragma unroll
            for (int q = 0; q < 4; q++) {
                if (q > 0) col += cv[q + 10] - cv[q - 1];
                int y = yg + q;
                if (y >= m + 5 + C) break;
                int gy = y0 - 15 + y, gx = x0 - 15 + x;
                float o = 0.f;
                if ((unsigned)gy < HH && (unsigned)gx < WW) {
                    float s = BA(y, x);
                    float e = fmaf(w, s - col * (1.0f / 121.0f), s);
                    o = (it < 2) ? fmaf(A, e, Bc) : e;
                }
                BA(y, x) = o;
            }
        }
    }
    __syncthreads();
    float* op = out + ((size_t)b * C2 + c) * HH * WW;
    for (int i = t; i < 64 * 64; i += 256) {
        int ly = i >> 6, lx = i & 63;
        op[(size_t)(y0 + ly) * WW + (x0 + lx)] = BA(15 + ly, 15 + lx);
    }
    #undef BA
    #undef BB
}

// ---------------------------------------------------------------------------
extern "C" void kernel_launch(void* const* d_in, const int* in_sizes, int n_in,
                              void* d_out, int out_size) {
    const float* x        = (const float*)d_in[0];
    const float* w1       = (const float*)d_in[1];
    const float* b1       = (const float*)d_in[2];
    const float* w2       = (const float*)d_in[3];
    const float* b2       = (const float*)d_in[4];
    const float* down_k   = (const float*)d_in[5];
    const float* down_b   = (const float*)d_in[6];
    const float* ft_gamma = (const float*)d_in[7];
    const float* ft_beta  = (const float*)d_in[8];
    const float* ft_mean  = (const float*)d_in[9];
    const float* ft_var   = (const float*)d_in[10];
    const float* ft_k     = (const float*)d_in[11];
    const float* ft_b     = (const float*)d_in[12];
    const float* emph_w   = (const float*)d_in[13];
    const float* interp_k = (const float*)d_in[14];
    const float* interp_b = (const float*)d_in[15];
    const float* i_gamma  = (const float*)d_in[16];
    const float* i_beta   = (const float*)d_in[17];
    const float* i_mean   = (const float*)d_in[18];
    const float* i_var    = (const float*)d_in[19];
    float* out = (float*)d_out;

    static int ft3_attr_set = 0;
    if (!ft3_attr_set) {
        cudaFuncSetAttribute(k_ft3, cudaFuncAttributeMaxDynamicSharedMemorySize,
                             2 * 94 * 95 * (int)sizeof(float));
        ft3_attr_set = 1;
    }

    k_bins<<<(BATCH*3*HH*WW/4 + 255)/256, 256>>>(x);
    k_mode<<<dim3(4, 36, 6), 128>>>();
    k_d1<<<dim3(11, N1, 2), dim3(16, 32)>>>(w1, b1, w2, b2, down_k, down_b);
    k_down<<<(BATCH * C2 * N2 * N2 + 255) / 256, 256>>>(2, down_k, down_b);
    k_down<<<(BATCH * C2 * N3 * N3 + 255) / 256, 256>>>(3, down_k, down_b);
    k_down<<<(BATCH * C2 * N4 * N4 + 255) / 256, 256>>>(4, down_k, down_b);
    k_down<<<(BATCH * C2 * N5 * N5 + 255) / 256, 256>>>(5, down_k, down_b);
    k_acc<<<dim3(16, 16, 64), dim3(32, 8)>>>(interp_k, interp_b, i_gamma, i_beta, i_mean, i_var);
    k_ft3<<<dim3(8, 8, 128), 256, 2 * 94 * 95 * (int)sizeof(float)>>>(
        out, ft_gamma, ft_beta, ft_mean, ft_var, ft_k, ft_b, emph_w);
}